// round 9
// baseline (speedup 1.0000x reference)
#include <cuda_runtime.h>
#include <cuda_bf16.h>
#include <cstdint>

#define NN 50000
#define DIMX 128
#define NE 800000

// ---- scratch (static __device__ globals; zero-initialized at load) ----
__device__ __nv_bfloat16 g_hb16[2][NN * DIMX];   // ping-pong hidden states (bf16)
__device__ __nv_bfloat16 g_aggb16[NN * DIMX];    // aggregation (bf16)
__device__ __nv_bfloat16 g_Wb16[3 * 2 * DIMX * DIMX]; // [layer][phase V/A][n][k]
__device__ int   g_off[NN + 1];
__device__ int   g_cnt[NN];     // degree counters; invariant: zero at launch entry
__device__ int   g_srt[NE];
__device__ int   g_bsum[64];
__device__ float g_ro_all[4][DIMX];   // readout per layer

// ================= helpers =================

__device__ __forceinline__ uint32_t smem_u32(const void* p) {
    uint32_t a;
    asm("{ .reg .u64 t; cvta.to.shared.u64 t, %1; cvt.u32.u64 %0, t; }"
        : "=r"(a) : "l"(p));
    return a;
}

__device__ __forceinline__ void ldm_x4(uint32_t* r, uint32_t addr) {
    asm volatile("ldmatrix.sync.aligned.m8n8.x4.shared.b16 {%0,%1,%2,%3}, [%4];"
                 : "=r"(r[0]), "=r"(r[1]), "=r"(r[2]), "=r"(r[3]) : "r"(addr));
}

__device__ __forceinline__ void mma_bf16(float* c, const uint32_t* a,
                                         const uint32_t* b) {
    asm volatile(
        "mma.sync.aligned.m16n8k16.row.col.f32.bf16.bf16.f32 "
        "{%0,%1,%2,%3}, {%4,%5,%6,%7}, {%8,%9}, {%0,%1,%2,%3};"
        : "+f"(c[0]), "+f"(c[1]), "+f"(c[2]), "+f"(c[3])
        : "r"(a[0]), "r"(a[1]), "r"(a[2]), "r"(a[3]), "r"(b[0]), "r"(b[1]));
}

__device__ __forceinline__ void cp16(uint32_t dst, const void* src, int sz) {
    asm volatile("cp.async.cg.shared.global [%0], [%1], 16, %2;"
                 :: "r"(dst), "l"(src), "r"(sz) : "memory");
}
#define CP_COMMIT() asm volatile("cp.async.commit_group;" ::: "memory")
#define CP_WAIT(N)  asm volatile("cp.async.wait_group %0;" :: "n"(N) : "memory")

__device__ __forceinline__ void acc_bf2(float& a0, float& a1, uint32_t w) {
    a0 += __uint_as_float(w << 16);
    a1 += __uint_as_float(w & 0xffff0000u);
}

__device__ __forceinline__ uint32_t pack_bf2(float lo, float hi) {
    uint32_t r;
    asm("cvt.rn.bf16x2.f32 %0, %1, %2;" : "=r"(r) : "f"(hi), "f"(lo));
    return r;
}

// ====== setup: copy_x + wconv + hist + zero ro + g_off[n] ======

__global__ void setup_kernel(const float* __restrict__ x,
                             const float* __restrict__ Vw,
                             const float* __restrict__ Aw,
                             const int* __restrict__ dst,
                             int n2, int n, int e) {
    int i = blockIdx.x * blockDim.x + threadIdx.x;
    if (i < n2) {
        float2 v = reinterpret_cast<const float2*>(x)[i];
        reinterpret_cast<uint32_t*>(g_hb16[0])[i] = pack_bf2(v.x, v.y);
    }
    if (i < 3 * 2 * DIMX * DIMX) {
        int l = i / (2 * DIMX * DIMX);
        int rem = i - l * 2 * DIMX * DIMX;
        int phase = rem >> 14;
        int el = rem & 16383;
        const float* W = phase ? Aw : Vw;
        g_Wb16[i] = __float2bfloat16_rn(W[l * DIMX * DIMX + el]);
    }
    if (i < e) atomicAdd(&g_cnt[dst[i]], 1);   // g_cnt zero on entry (invariant)
    if (i < 4 * DIMX) ((float*)g_ro_all)[i] = 0.0f;
    if (i == 0) g_off[n] = e;
}

// ================= CSR build =================

__global__ void scan1_kernel(int n) {
    __shared__ int s[1024];
    int i = blockIdx.x * 1024 + threadIdx.x;
    int v = (i < n) ? g_cnt[i] : 0;
    s[threadIdx.x] = v;
    __syncthreads();
    for (int off = 1; off < 1024; off <<= 1) {
        int t = (threadIdx.x >= off) ? s[threadIdx.x - off] : 0;
        __syncthreads();
        s[threadIdx.x] += t;
        __syncthreads();
    }
    if (i < n) g_off[i] = s[threadIdx.x] - v;
    if (threadIdx.x == 1023) g_bsum[blockIdx.x] = s[1023];
}

// scan3: add cross-block prefix (computed inline from <=64 partials)
__global__ void scan3_kernel(int n) {
    __shared__ int spre[2];
    int tid = threadIdx.x;
    if (tid < 64) {
        int v = (tid < blockIdx.x) ? g_bsum[tid] : 0;
#pragma unroll
        for (int o = 16; o; o >>= 1) v += __shfl_xor_sync(0xffffffffu, v, o);
        if ((tid & 31) == 0) spre[tid >> 5] = v;
    }
    __syncthreads();
    int pre = spre[0] + spre[1];
    int i = blockIdx.x * 1024 + tid;
    if (i < n) g_off[i] += pre;
}

// scatter: atomic countdown leaves g_cnt zeroed for the next replay
__global__ void scatter_kernel(const int* __restrict__ src,
                               const int* __restrict__ dst, int e) {
    int i = blockIdx.x * blockDim.x + threadIdx.x;
    if (i < e) {
        int d = dst[i];
        int pos = g_off[d] + atomicAdd(&g_cnt[d], -1) - 1;
        g_srt[pos] = src[i];
    }
}

// ================= readout of layer-0 input =================

__global__ void readout0_kernel(int n) {
    const __nv_bfloat16* __restrict__ h = g_hb16[0];
    int j = threadIdx.x;  // 128
    float s = 0.0f;
    for (int i = blockIdx.x; i < n; i += gridDim.x)
        s += __bfloat162float(h[i * DIMX + j]);
    atomicAdd(&g_ro_all[0][j], s);
}

// ========== aggregation: TWO warps per node (half-row each, 4 edge lanes) ======
// agg[i] = h[i] + sum_{e in csr(i)} h[srt[e]]

__global__ void __launch_bounds__(256)
agg_kernel(int insel, int n) {
    int gw = (blockIdx.x * blockDim.x + threadIdx.x) >> 5;
    int w = gw >> 1;          // node
    if (w >= n) return;
    int hf = gw & 1;          // half-row (128B)
    int lane = threadIdx.x & 31;
    int c = hf * 8 + (lane & 7);  // 16B chunk within 256B row
    int p = lane >> 3;            // edge parity 0..3
    const uint4* __restrict__ h4 =
        reinterpret_cast<const uint4*>(g_hb16[insel]);

    float a[8];
#pragma unroll
    for (int k = 0; k < 8; k++) a[k] = 0.0f;

    if (p == 0) {  // self row counted once
        uint4 v = h4[(size_t)w * 16 + c];
        acc_bf2(a[0], a[1], v.x);
        acc_bf2(a[2], a[3], v.y);
        acc_bf2(a[4], a[5], v.z);
        acc_bf2(a[6], a[7], v.w);
    }

    int beg = g_off[w], end = g_off[w + 1];
    int e = beg + p;
    for (; e + 4 < end; e += 8) {
        int r0 = g_srt[e];
        int r1 = g_srt[e + 4];
        uint4 v0 = h4[(size_t)r0 * 16 + c];
        uint4 v1 = h4[(size_t)r1 * 16 + c];
        acc_bf2(a[0], a[1], v0.x); acc_bf2(a[2], a[3], v0.y);
        acc_bf2(a[4], a[5], v0.z); acc_bf2(a[6], a[7], v0.w);
        acc_bf2(a[0], a[1], v1.x); acc_bf2(a[2], a[3], v1.y);
        acc_bf2(a[4], a[5], v1.z); acc_bf2(a[6], a[7], v1.w);
    }
    if (e < end) {
        int r0 = g_srt[e];
        uint4 v0 = h4[(size_t)r0 * 16 + c];
        acc_bf2(a[0], a[1], v0.x); acc_bf2(a[2], a[3], v0.y);
        acc_bf2(a[4], a[5], v0.z); acc_bf2(a[6], a[7], v0.w);
    }

    // combine the 4 edge-parity groups (lanes differing in bits 3,4)
#pragma unroll
    for (int k = 0; k < 8; k++) {
        a[k] += __shfl_xor_sync(0xffffffffu, a[k], 8);
        a[k] += __shfl_xor_sync(0xffffffffu, a[k], 16);
    }

    if (p == 0) {
        uint4 o;
        o.x = pack_bf2(a[0], a[1]);
        o.y = pack_bf2(a[2], a[3]);
        o.z = pack_bf2(a[4], a[5]);
        o.w = pack_bf2(a[6], a[7]);
        reinterpret_cast<uint4*>(g_aggb16)[(size_t)w * 16 + c] = o;
    }
}

// ====== HMMA bf16 GEMM (M=64 tiles), cp.async pipelined; bias fused; head on l==2
// h_out = relu([h|agg] @ [Vw;Aw]^T + bias); bias = Vb+Ab+Rb + ro@Rw^T.
// 4 K-chunks of 64; double-buffered (2 x 24KB: A 8KB + B 16KB).

#define S_BIAS 49152
#define S_DOT  49664
#define S_OW   50176
#define GEMM_SMEM 51200

__global__ void __launch_bounds__(256, 3)
gemm_mma_kernel(int insel, int outsel, int l, int n,
                const float* __restrict__ Vb, const float* __restrict__ Ab,
                const float* __restrict__ Rb, const float* __restrict__ Rw,
                const float* __restrict__ ow, const float* __restrict__ ob,
                float* __restrict__ out) {
    extern __shared__ char smem[];
    float* sbias = (float*)(smem + S_BIAS);
    float* sdot  = (float*)(smem + S_DOT);
    float* sow   = (float*)(smem + S_OW);
    const int tid = threadIdx.x;
    const int wid = tid >> 5, lane = tid & 31;
    const int bm = blockIdx.x * 64;
    const int wm = (wid & 1) * 32;
    const int wn = (wid >> 1) * 32;
    const uint32_t sbase = smem_u32(smem);

    const __nv_bfloat16* __restrict__ A0 = g_hb16[insel];
    const __nv_bfloat16* __restrict__ A1 = g_aggb16;
    const __nv_bfloat16* __restrict__ W = g_Wb16 + (size_t)l * 32768;

    // ---- prefetch one K=64 chunk (A 8KB + B 16KB) into buffer buf ----
    auto prefetch = [&](int cs, int buf) {
        const __nv_bfloat16* __restrict__ Asrc = (cs < 2) ? A0 : A1;
        const __nv_bfloat16* __restrict__ Bsrc = W + ((cs >> 1) << 14);
        const int k0 = (cs & 1) * 64;
        const uint32_t sA = sbase + buf * 24576;
        const uint32_t sB = sA + 8192;
#pragma unroll
        for (int t = 0; t < 2; t++) {  // A: 64 rows x 8 chunks = 512
            int idx = tid + t * 256;
            int row = idx >> 3, cc = idx & 7;
            uint32_t so = (uint32_t)(row * 128 + ((cc ^ (row & 7)) << 4));
            int gm = bm + row;
            int gmc = gm < n ? gm : 0;
            cp16(sA + so, Asrc + (size_t)gmc * DIMX + k0 + cc * 8,
                 gm < n ? 16 : 0);
        }
#pragma unroll
        for (int t = 0; t < 4; t++) {  // B: 128 rows x 8 chunks = 1024
            int idx = tid + t * 256;
            int row = idx >> 3, cc = idx & 7;
            uint32_t so = (uint32_t)(row * 128 + ((cc ^ (row & 7)) << 4));
            cp16(sB + so, Bsrc + row * DIMX + k0 + cc * 8, 16);
        }
        CP_COMMIT();
    };

    float acc[2][4][4];
#pragma unroll
    for (int a = 0; a < 2; a++)
#pragma unroll
        for (int b = 0; b < 4; b++)
#pragma unroll
            for (int c = 0; c < 4; c++) acc[a][b][c] = 0.0f;

    prefetch(0, 0);
    prefetch(1, 1);

    // bias while loads are in flight
    if (tid < 128) {
        float b = Vb[l * DIMX + tid] + Ab[l * DIMX + tid] + Rb[l * DIMX + tid];
        const float* __restrict__ ro = g_ro_all[l];
        const float* __restrict__ rw = Rw + (size_t)l * DIMX * DIMX
                                          + (size_t)tid * DIMX;
#pragma unroll 8
        for (int k = 0; k < DIMX; k++) b += ro[k] * rw[k];
        sbias[tid] = b;
    }
    if (l == 2) {
        if (tid < 128) sdot[tid] = 0.0f;
        if (tid < 256) sow[tid] = ow[tid];
    }

    auto compute = [&](int buf) {
        const uint32_t sA = sbase + buf * 24576;
        const uint32_t sB = sA + 8192;
#pragma unroll
        for (int ks = 0; ks < 4; ks++) {
            const int kc = ks * 2;
            uint32_t a[2][4], b[2][4];
#pragma unroll
            for (int mi = 0; mi < 2; mi++) {
                int row = wm + mi * 16 + (lane & 15);
                int c = kc + (lane >> 4);
                ldm_x4(a[mi], sA + row * 128 + ((c ^ (row & 7)) << 4));
            }
#pragma unroll
            for (int nj = 0; nj < 2; nj++) {
                int row = wn + nj * 16 + ((lane >> 4) << 3) + (lane & 7);
                int c = kc + ((lane >> 3) & 1);
                ldm_x4(b[nj], sB + row * 128 + ((c ^ (row & 7)) << 4));
            }
#pragma unroll
            for (int mi = 0; mi < 2; mi++) {
                mma_bf16(acc[mi][0], a[mi], &b[0][0]);
                mma_bf16(acc[mi][1], a[mi], &b[0][2]);
                mma_bf16(acc[mi][2], a[mi], &b[1][0]);
                mma_bf16(acc[mi][3], a[mi], &b[1][2]);
            }
        }
    };

    CP_WAIT(1); __syncthreads();
    compute(0);
    __syncthreads(); prefetch(2, 0);
    CP_WAIT(1); __syncthreads();
    compute(1);
    __syncthreads(); prefetch(3, 1);
    CP_WAIT(1); __syncthreads();
    compute(0);
    CP_WAIT(0); __syncthreads();
    compute(1);

    // ---- epilogue ----
    const int qr = lane >> 2;
    const int qc = (lane & 3) * 2;

    if (l < 2) {
        __nv_bfloat16* __restrict__ O = g_hb16[outsel];
        float* __restrict__ ro_next = g_ro_all[l + 1];
        float colsum[4][2];
#pragma unroll
        for (int ni = 0; ni < 4; ni++) colsum[ni][0] = colsum[ni][1] = 0.0f;
#pragma unroll
        for (int mi = 0; mi < 2; mi++) {
            int r0 = bm + wm + mi * 16 + qr;
#pragma unroll
            for (int ni = 0; ni < 4; ni++) {
                int col = wn + ni * 8 + qc;
                float b0 = sbias[col], b1 = sbias[col + 1];
                float v0 = fmaxf(acc[mi][ni][0] + b0, 0.f);
                float v1 = fmaxf(acc[mi][ni][1] + b1, 0.f);
                float v2 = fmaxf(acc[mi][ni][2] + b0, 0.f);
                float v3 = fmaxf(acc[mi][ni][3] + b1, 0.f);
                if (r0 < n) {
                    *(uint32_t*)(O + (size_t)r0 * DIMX + col) = pack_bf2(v0, v1);
                    colsum[ni][0] += v0; colsum[ni][1] += v1;
                }
                if (r0 + 8 < n) {
                    *(uint32_t*)(O + (size_t)(r0 + 8) * DIMX + col) =
                        pack_bf2(v2, v3);
                    colsum[ni][0] += v2; colsum[ni][1] += v3;
                }
            }
        }
#pragma unroll
        for (int ni = 0; ni < 4; ni++)
#pragma unroll
            for (int j = 0; j < 2; j++) {
                float v = colsum[ni][j];
                v += __shfl_xor_sync(0xffffffffu, v, 4);
                v += __shfl_xor_sync(0xffffffffu, v, 8);
                v += __shfl_xor_sync(0xffffffffu, v, 16);
                if (lane < 4)
                    atomicAdd(&ro_next[wn + ni * 8 + lane * 2 + j], v);
            }
    } else {
        // final layer: sigmoid head fused; no h store, no readout
#pragma unroll
        for (int mi = 0; mi < 2; mi++) {
            int rl = wm + mi * 16 + qr;
            int r0 = bm + rl;
            float dA0 = 0.f, dA1 = 0.f, dB0 = 0.f, dB1 = 0.f;
#pragma unroll
            for (int ni = 0; ni < 4; ni++) {
                int col = wn + ni * 8 + qc;
                float b0 = sbias[col], b1 = sbias[col + 1];
                float w0 = sow[col], w1 = sow[col + 1];
                float u0 = sow[128 + col], u1 = sow[128 + col + 1];
                float v0 = fmaxf(acc[mi][ni][0] + b0, 0.f);
                float v1 = fmaxf(acc[mi][ni][1] + b1, 0.f);
                float v2 = fmaxf(acc[mi][ni][2] + b0, 0.f);
                float v3 = fmaxf(acc[mi][ni][3] + b1, 0.f);
                dA0 += v0 * w0 + v1 * w1;
                dA1 += v0 * u0 + v1 * u1;
                dB0 += v2 * w0 + v3 * w1;
                dB1 += v2 * u0 + v3 * u1;
            }
            if (r0 < n) {
                atomicAdd(&sdot[rl * 2 + 0], dA0);
                atomicAdd(&sdot[rl * 2 + 1], dA1);
            }
            if (r0 + 8 < n) {
                atomicAdd(&sdot[(rl + 8) * 2 + 0], dB0);
                atomicAdd(&sdot[(rl + 8) * 2 + 1], dB1);
            }
        }
        __syncthreads();
        if (tid < 64) {
            int gm = bm + tid;
            if (gm < n) {
                float z0 = sdot[tid * 2 + 0] + ob[0];
                float z1 = sdot[tid * 2 + 1] + ob[1];
                float2 o;
                o.x = 1.0f / (1.0f + __expf(-z0));
                o.y = 1.0f / (1.0f + __expf(-z1));
                *(float2*)(out + (size_t)gm * 2) = o;
            }
        }
    }
}

// ================= launch =================

extern "C" void kernel_launch(void* const* d_in, const int* in_sizes, int n_in,
                              void* d_out, int out_size) {
    const float* x  = (const float*)d_in[0];
    const int* src  = (const int*)d_in[1];
    const int* dst  = (const int*)d_in[2];
    const float* Vw = (const float*)d_in[3];
    const float* Vb = (const float*)d_in[4];
    const float* Aw = (const float*)d_in[5];
    const float* Ab = (const float*)d_in[6];
    const float* Rw = (const float*)d_in[7];
    const float* Rb = (const float*)d_in[8];
    const float* ow = (const float*)d_in[9];
    const float* ob = (const float*)d_in[10];
    float* out = (float*)d_out;

    const int n = in_sizes[0] / DIMX;   // 50000
    const int e = in_sizes[1];          // 800000

    cudaFuncSetAttribute(gemm_mma_kernel,
                         cudaFuncAttributeMaxDynamicSharedMemorySize, GEMM_SMEM);

    int n2 = (n * DIMX) / 2;
    setup_kernel<<<(n2 + 255) / 256, 256>>>(x, Vw, Aw, dst, n2, n, e);

    int nb = (n + 1023) / 1024;
    scan1_kernel<<<nb, 1024>>>(n);
    scan3_kernel<<<nb, 1024>>>(n);
    scatter_kernel<<<(e + 255) / 256, 256>>>(src, dst, e);
    readout0_kernel<<<512, 128>>>(n);

    for (int l = 0; l < 3; l++) {
        int insel = l & 1;       // 0,1,0
        int outsel = insel ^ 1;  // 1,0,1
        agg_kernel<<<(n + 3) / 4, 256>>>(insel, n);
        gemm_mma_kernel<<<(n + 63) / 64, 256, GEMM_SMEM>>>(
            insel, outsel, l, n, Vb, Ab, Rb, Rw, ow, ob, out);
    }
}

// round 10
// speedup vs baseline: 1.3997x; 1.3997x over previous
#include <cuda_runtime.h>
#include <cuda_bf16.h>
#include <cstdint>

#define NN 50000
#define DIMX 128
#define NE 800000

// ---- scratch (static __device__ globals; zero-initialized at load) ----
__device__ __nv_bfloat16 g_hb16[2][NN * DIMX];   // ping-pong hidden states (bf16)
__device__ __nv_bfloat16 g_aggb16[NN * DIMX];    // aggregation (bf16)
__device__ __nv_bfloat16 g_Wb16[3 * 2 * DIMX * DIMX]; // [layer][phase V/A][n][k]
__device__ int   g_off[NN + 1];
__device__ int   g_cnt[NN];     // degree counters; invariant: zero at launch entry
__device__ int   g_srt[NE];
__device__ int   g_bsum[64];
__device__ float g_ro_all[4][DIMX];   // readout per layer

// ================= helpers =================

__device__ __forceinline__ uint32_t smem_u32(const void* p) {
    uint32_t a;
    asm("{ .reg .u64 t; cvta.to.shared.u64 t, %1; cvt.u32.u64 %0, t; }"
        : "=r"(a) : "l"(p));
    return a;
}

__device__ __forceinline__ void ldm_x4(uint32_t* r, uint32_t addr) {
    asm volatile("ldmatrix.sync.aligned.m8n8.x4.shared.b16 {%0,%1,%2,%3}, [%4];"
                 : "=r"(r[0]), "=r"(r[1]), "=r"(r[2]), "=r"(r[3]) : "r"(addr));
}

__device__ __forceinline__ void mma_bf16(float* c, const uint32_t* a,
                                         const uint32_t* b) {
    asm volatile(
        "mma.sync.aligned.m16n8k16.row.col.f32.bf16.bf16.f32 "
        "{%0,%1,%2,%3}, {%4,%5,%6,%7}, {%8,%9}, {%0,%1,%2,%3};"
        : "+f"(c[0]), "+f"(c[1]), "+f"(c[2]), "+f"(c[3])
        : "r"(a[0]), "r"(a[1]), "r"(a[2]), "r"(a[3]), "r"(b[0]), "r"(b[1]));
}

__device__ __forceinline__ void cp16(uint32_t dst, const void* src, int sz) {
    asm volatile("cp.async.cg.shared.global [%0], [%1], 16, %2;"
                 :: "r"(dst), "l"(src), "r"(sz) : "memory");
}
#define CP_COMMIT() asm volatile("cp.async.commit_group;" ::: "memory")
#define CP_WAIT(N)  asm volatile("cp.async.wait_group %0;" :: "n"(N) : "memory")

__device__ __forceinline__ void acc_bf2(float& a0, float& a1, uint32_t w) {
    a0 += __uint_as_float(w << 16);
    a1 += __uint_as_float(w & 0xffff0000u);
}

__device__ __forceinline__ uint32_t pack_bf2(float lo, float hi) {
    uint32_t r;
    asm("cvt.rn.bf16x2.f32 %0, %1, %2;" : "=r"(r) : "f"(hi), "f"(lo));
    return r;
}

// ====== setup: copy_x + wconv + hist + zero ro + g_off[n] ======

__global__ void setup_kernel(const float* __restrict__ x,
                             const float* __restrict__ Vw,
                             const float* __restrict__ Aw,
                             const int* __restrict__ dst,
                             int n2, int n, int e) {
    int i = blockIdx.x * blockDim.x + threadIdx.x;
    if (i < n2) {
        float2 v = reinterpret_cast<const float2*>(x)[i];
        reinterpret_cast<uint32_t*>(g_hb16[0])[i] = pack_bf2(v.x, v.y);
    }
    if (i < 3 * 2 * DIMX * DIMX) {
        int l = i / (2 * DIMX * DIMX);
        int rem = i - l * 2 * DIMX * DIMX;
        int phase = rem >> 14;
        int el = rem & 16383;
        const float* W = phase ? Aw : Vw;
        g_Wb16[i] = __float2bfloat16_rn(W[l * DIMX * DIMX + el]);
    }
    if (i < e) atomicAdd(&g_cnt[dst[i]], 1);   // g_cnt zero on entry (invariant)
    if (i < 4 * DIMX) ((float*)g_ro_all)[i] = 0.0f;
    if (i == 0) g_off[n] = e;
}

// ================= CSR build =================

__global__ void scan1_kernel(int n) {
    __shared__ int s[1024];
    int i = blockIdx.x * 1024 + threadIdx.x;
    int v = (i < n) ? g_cnt[i] : 0;
    s[threadIdx.x] = v;
    __syncthreads();
    for (int off = 1; off < 1024; off <<= 1) {
        int t = (threadIdx.x >= off) ? s[threadIdx.x - off] : 0;
        __syncthreads();
        s[threadIdx.x] += t;
        __syncthreads();
    }
    if (i < n) g_off[i] = s[threadIdx.x] - v;
    if (threadIdx.x == 1023) g_bsum[blockIdx.x] = s[1023];
}

// scan3: add cross-block prefix (computed inline from <=64 partials)
__global__ void scan3_kernel(int n) {
    __shared__ int spre[2];
    int tid = threadIdx.x;
    if (tid < 64) {
        int v = (tid < blockIdx.x) ? g_bsum[tid] : 0;
#pragma unroll
        for (int o = 16; o; o >>= 1) v += __shfl_xor_sync(0xffffffffu, v, o);
        if ((tid & 31) == 0) spre[tid >> 5] = v;
    }
    __syncthreads();
    int pre = spre[0] + spre[1];
    int i = blockIdx.x * 1024 + tid;
    if (i < n) g_off[i] += pre;
}

// scatter: atomic countdown leaves g_cnt zeroed for the next replay
__global__ void scatter_kernel(const int* __restrict__ src,
                               const int* __restrict__ dst, int e) {
    int i = blockIdx.x * blockDim.x + threadIdx.x;
    if (i < e) {
        int d = dst[i];
        int pos = g_off[d] + atomicAdd(&g_cnt[d], -1) - 1;
        g_srt[pos] = src[i];
    }
}

// ================= readout of layer-0 input =================

__global__ void readout0_kernel(int n) {
    const __nv_bfloat16* __restrict__ h = g_hb16[0];
    int j = threadIdx.x;  // 128
    float s = 0.0f;
    for (int i = blockIdx.x; i < n; i += gridDim.x)
        s += __bfloat162float(h[i * DIMX + j]);
    atomicAdd(&g_ro_all[0][j], s);
}

// ================= aggregation: warp per node, uint4 gathers =================
// agg[i] = h[i] + sum_{e in csr(i)} h[srt[e]]   (4 loads in flight per lane)

__global__ void __launch_bounds__(256)
agg_kernel(int insel, int n) {
    int w = (blockIdx.x * blockDim.x + threadIdx.x) >> 5;
    if (w >= n) return;
    int lane = threadIdx.x & 31;
    int c = lane & 15;   // 16B chunk within 256B row
    int p = lane >> 4;   // edge parity
    const uint4* __restrict__ h4 =
        reinterpret_cast<const uint4*>(g_hb16[insel]);

    float a[8];
#pragma unroll
    for (int k = 0; k < 8; k++) a[k] = 0.0f;

    if (p == 0) {  // self row counted once
        uint4 v = h4[(size_t)w * 16 + c];
        acc_bf2(a[0], a[1], v.x);
        acc_bf2(a[2], a[3], v.y);
        acc_bf2(a[4], a[5], v.z);
        acc_bf2(a[6], a[7], v.w);
    }

    int beg = g_off[w], end = g_off[w + 1];
    int e = beg + p;
    // 4 outstanding gathers per lane per iteration
    for (; e + 6 < end; e += 8) {
        int r0 = g_srt[e];
        int r1 = g_srt[e + 2];
        int r2 = g_srt[e + 4];
        int r3 = g_srt[e + 6];
        uint4 v0 = h4[(size_t)r0 * 16 + c];
        uint4 v1 = h4[(size_t)r1 * 16 + c];
        uint4 v2 = h4[(size_t)r2 * 16 + c];
        uint4 v3 = h4[(size_t)r3 * 16 + c];
        acc_bf2(a[0], a[1], v0.x); acc_bf2(a[2], a[3], v0.y);
        acc_bf2(a[4], a[5], v0.z); acc_bf2(a[6], a[7], v0.w);
        acc_bf2(a[0], a[1], v1.x); acc_bf2(a[2], a[3], v1.y);
        acc_bf2(a[4], a[5], v1.z); acc_bf2(a[6], a[7], v1.w);
        acc_bf2(a[0], a[1], v2.x); acc_bf2(a[2], a[3], v2.y);
        acc_bf2(a[4], a[5], v2.z); acc_bf2(a[6], a[7], v2.w);
        acc_bf2(a[0], a[1], v3.x); acc_bf2(a[2], a[3], v3.y);
        acc_bf2(a[4], a[5], v3.z); acc_bf2(a[6], a[7], v3.w);
    }
    for (; e < end; e += 2) {
        int r0 = g_srt[e];
        uint4 v0 = h4[(size_t)r0 * 16 + c];
        acc_bf2(a[0], a[1], v0.x); acc_bf2(a[2], a[3], v0.y);
        acc_bf2(a[4], a[5], v0.z); acc_bf2(a[6], a[7], v0.w);
    }

    // combine the two edge-parity halves
#pragma unroll
    for (int k = 0; k < 8; k++)
        a[k] += __shfl_xor_sync(0xffffffffu, a[k], 16);

    if (p == 0) {
        uint4 o;
        o.x = pack_bf2(a[0], a[1]);
        o.y = pack_bf2(a[2], a[3]);
        o.z = pack_bf2(a[4], a[5]);
        o.w = pack_bf2(a[6], a[7]);
        reinterpret_cast<uint4*>(g_aggb16)[(size_t)w * 16 + c] = o;
    }
}

// ====== HMMA bf16 GEMM, cp.async pipelined; bias fused; head fused on l==2 ======
// h_out = relu([h|agg] @ [Vw;Aw]^T + bias); bias = Vb+Ab+Rb + ro@Rw^T.
// 4 K-chunks of 64; double-buffered (2 x 32KB). l==2: sigmoid head, no h store.

#define S_BIAS 65536
#define S_DOT  66048
#define S_OW   67072
#define GEMM_SMEM 68096

__global__ void __launch_bounds__(256, 2)
gemm_mma_kernel(int insel, int outsel, int l, int n,
                const float* __restrict__ Vb, const float* __restrict__ Ab,
                const float* __restrict__ Rb, const float* __restrict__ Rw,
                const float* __restrict__ ow, const float* __restrict__ ob,
                float* __restrict__ out) {
    extern __shared__ char smem[];
    float* sbias = (float*)(smem + S_BIAS);
    float* sdot  = (float*)(smem + S_DOT);
    float* sow   = (float*)(smem + S_OW);
    const int tid = threadIdx.x;
    const int wid = tid >> 5, lane = tid & 31;
    const int bm = blockIdx.x * 128;
    const int wm = (wid & 1) * 64;
    const int wn = (wid >> 1) * 32;
    const uint32_t sbase = smem_u32(smem);

    const __nv_bfloat16* __restrict__ A0 = g_hb16[insel];
    const __nv_bfloat16* __restrict__ A1 = g_aggb16;
    const __nv_bfloat16* __restrict__ W = g_Wb16 + (size_t)l * 32768;

    // ---- prefetch one K=64 chunk (A 16KB + B 16KB) into buffer buf ----
    auto prefetch = [&](int cs, int buf) {
        const __nv_bfloat16* __restrict__ Asrc = (cs < 2) ? A0 : A1;
        const __nv_bfloat16* __restrict__ Bsrc = W + ((cs >> 1) << 14);
        const int k0 = (cs & 1) * 64;
        const uint32_t sA = sbase + buf * 32768;
        const uint32_t sB = sA + 16384;
#pragma unroll
        for (int t = 0; t < 4; t++) {
            int idx = tid + t * 256;
            int row = idx >> 3, cc = idx & 7;
            uint32_t so = (uint32_t)(row * 128 + ((cc ^ (row & 7)) << 4));
            int gm = bm + row;
            int gmc = gm < n ? gm : 0;
            cp16(sA + so, Asrc + (size_t)gmc * DIMX + k0 + cc * 8,
                 gm < n ? 16 : 0);
            cp16(sB + so, Bsrc + row * DIMX + k0 + cc * 8, 16);
        }
        CP_COMMIT();
    };

    float acc[4][4][4];
#pragma unroll
    for (int a = 0; a < 4; a++)
#pragma unroll
        for (int b = 0; b < 4; b++)
#pragma unroll
            for (int c = 0; c < 4; c++) acc[a][b][c] = 0.0f;

    prefetch(0, 0);
    prefetch(1, 1);

    // bias while loads are in flight
    if (tid < 128) {
        float b = Vb[l * DIMX + tid] + Ab[l * DIMX + tid] + Rb[l * DIMX + tid];
        const float* __restrict__ ro = g_ro_all[l];
        const float* __restrict__ rw = Rw + (size_t)l * DIMX * DIMX
                                          + (size_t)tid * DIMX;
#pragma unroll 8
        for (int k = 0; k < DIMX; k++) b += ro[k] * rw[k];
        sbias[tid] = b;
    }
    if (l == 2) {
        sdot[tid] = 0.0f;
        sow[tid] = ow[tid];
    }

    auto compute = [&](int buf) {
        const uint32_t sA = sbase + buf * 32768;
        const uint32_t sB = sA + 16384;
#pragma unroll
        for (int ks = 0; ks < 4; ks++) {
            const int kc = ks * 2;
            uint32_t a[4][4], b[2][4];
#pragma unroll
            for (int mi = 0; mi < 4; mi++) {
                int row = wm + mi * 16 + (lane & 15);
                int c = kc + (lane >> 4);
                ldm_x4(a[mi], sA + row * 128 + ((c ^ (row & 7)) << 4));
            }
#pragma unroll
            for (int nj = 0; nj < 2; nj++) {
                int row = wn + nj * 16 + ((lane >> 4) << 3) + (lane & 7);
                int c = kc + ((lane >> 3) & 1);
                ldm_x4(b[nj], sB + row * 128 + ((c ^ (row & 7)) << 4));
            }
#pragma unroll
            for (int mi = 0; mi < 4; mi++) {
                mma_bf16(acc[mi][0], a[mi], &b[0][0]);
                mma_bf16(acc[mi][1], a[mi], &b[0][2]);
                mma_bf16(acc[mi][2], a[mi], &b[1][0]);
                mma_bf16(acc[mi][3], a[mi], &b[1][2]);
            }
        }
    };

    CP_WAIT(1); __syncthreads();
    compute(0);
    __syncthreads(); prefetch(2, 0);
    CP_WAIT(1); __syncthreads();
    compute(1);
    __syncthreads(); prefetch(3, 1);
    CP_WAIT(1); __syncthreads();
    compute(0);
    CP_WAIT(0); __syncthreads();
    compute(1);

    // ---- epilogue ----
    const int qr = lane >> 2;
    const int qc = (lane & 3) * 2;

    if (l < 2) {
        __nv_bfloat16* __restrict__ O = g_hb16[outsel];
        float* __restrict__ ro_next = g_ro_all[l + 1];
        float colsum[4][2];
#pragma unroll
        for (int ni = 0; ni < 4; ni++) colsum[ni][0] = colsum[ni][1] = 0.0f;
#pragma unroll
        for (int mi = 0; mi < 4; mi++) {
            int r0 = bm + wm + mi * 16 + qr;
#pragma unroll
            for (int ni = 0; ni < 4; ni++) {
                int col = wn + ni * 8 + qc;
                float b0 = sbias[col], b1 = sbias[col + 1];
                float v0 = fmaxf(acc[mi][ni][0] + b0, 0.f);
                float v1 = fmaxf(acc[mi][ni][1] + b1, 0.f);
                float v2 = fmaxf(acc[mi][ni][2] + b0, 0.f);
                float v3 = fmaxf(acc[mi][ni][3] + b1, 0.f);
                if (r0 < n) {
                    *(uint32_t*)(O + (size_t)r0 * DIMX + col) = pack_bf2(v0, v1);
                    colsum[ni][0] += v0; colsum[ni][1] += v1;
                }
                if (r0 + 8 < n) {
                    *(uint32_t*)(O + (size_t)(r0 + 8) * DIMX + col) =
                        pack_bf2(v2, v3);
                    colsum[ni][0] += v2; colsum[ni][1] += v3;
                }
            }
        }
#pragma unroll
        for (int ni = 0; ni < 4; ni++)
#pragma unroll
            for (int j = 0; j < 2; j++) {
                float v = colsum[ni][j];
                v += __shfl_xor_sync(0xffffffffu, v, 4);
                v += __shfl_xor_sync(0xffffffffu, v, 8);
                v += __shfl_xor_sync(0xffffffffu, v, 16);
                if (lane < 4)
                    atomicAdd(&ro_next[wn + ni * 8 + lane * 2 + j], v);
            }
    } else {
        // final layer: sigmoid head fused; no h store, no readout
#pragma unroll
        for (int mi = 0; mi < 4; mi++) {
            int rl = wm + mi * 16 + qr;
            int r0 = bm + rl;
            float dA0 = 0.f, dA1 = 0.f, dB0 = 0.f, dB1 = 0.f;
#pragma unroll
            for (int ni = 0; ni < 4; ni++) {
                int col = wn + ni * 8 + qc;
                float b0 = sbias[col], b1 = sbias[col + 1];
                float w0 = sow[col], w1 = sow[col + 1];
                float u0 = sow[128 + col], u1 = sow[128 + col + 1];
                float v0 = fmaxf(acc[mi][ni][0] + b0, 0.f);
                float v1 = fmaxf(acc[mi][ni][1] + b1, 0.f);
                float v2 = fmaxf(acc[mi][ni][2] + b0, 0.f);
                float v3 = fmaxf(acc[mi][ni][3] + b1, 0.f);
                dA0 += v0 * w0 + v1 * w1;
                dA1 += v0 * u0 + v1 * u1;
                dB0 += v2 * w0 + v3 * w1;
                dB1 += v2 * u0 + v3 * u1;
            }
            if (r0 < n) {
                atomicAdd(&sdot[rl * 2 + 0], dA0);
                atomicAdd(&sdot[rl * 2 + 1], dA1);
            }
            if (r0 + 8 < n) {
                atomicAdd(&sdot[(rl + 8) * 2 + 0], dB0);
                atomicAdd(&sdot[(rl + 8) * 2 + 1], dB1);
            }
        }
        __syncthreads();
        if (tid < 128) {
            int gm = bm + tid;
            if (gm < n) {
                float z0 = sdot[tid * 2 + 0] + ob[0];
                float z1 = sdot[tid * 2 + 1] + ob[1];
                float2 o;
                o.x = 1.0f / (1.0f + __expf(-z0));
                o.y = 1.0f / (1.0f + __expf(-z1));
                *(float2*)(out + (size_t)gm * 2) = o;
            }
        }
    }
}

// ================= launch =================

extern "C" void kernel_launch(void* const* d_in, const int* in_sizes, int n_in,
                              void* d_out, int out_size) {
    const float* x  = (const float*)d_in[0];
    const int* src  = (const int*)d_in[1];
    const int* dst  = (const int*)d_in[2];
    const float* Vw = (const float*)d_in[3];
    const float* Vb = (const float*)d_in[4];
    const float* Aw = (const float*)d_in[5];
    const float* Ab = (const float*)d_in[6];
    const float* Rw = (const float*)d_in[7];
    const float* Rb = (const float*)d_in[8];
    const float* ow = (const float*)d_in[9];
    const float* ob = (const float*)d_in[10];
    float* out = (float*)d_out;

    const int n = in_sizes[0] / DIMX;   // 50000
    const int e = in_sizes[1];          // 800000

    cudaFuncSetAttribute(gemm_mma_kernel,
                         cudaFuncAttributeMaxDynamicSharedMemorySize, GEMM_SMEM);

    int n2 = (n * DIMX) / 2;
    setup_kernel<<<(n2 + 255) / 256, 256>>>(x, Vw, Aw, dst, n2, n, e);

    int nb = (n + 1023) / 1024;
    scan1_kernel<<<nb, 1024>>>(n);
    scan3_kernel<<<nb, 1024>>>(n);
    scatter_kernel<<<(e + 255) / 256, 256>>>(src, dst, e);
    readout0_kernel<<<512, 128>>>(n);

    for (int l = 0; l < 3; l++) {
        int insel = l & 1;       // 0,1,0
        int outsel = insel ^ 1;  // 1,0,1
        agg_kernel<<<(n * 32 + 255) / 256, 256>>>(insel, n);
        gemm_mma_kernel<<<(n + 127) / 128, 256, GEMM_SMEM>>>(
            insel, outsel, l, n, Vb, Ab, Rb, Rw, ow, ob, out);
    }
}